// round 11
// baseline (speedup 1.0000x reference)
#include <cuda_runtime.h>
#include <math.h>

#define C_CH   512
#define S_SP   4096
#define NHEADS 8
#define HD     64
#define NGROUPS 8
#define GROUP_ELEMS ((C_CH / NGROUPS) * S_SP)   // 64 ch * 4096 = 262144

typedef unsigned long long u64;

// ---------------- packed fp32x2 helpers (Blackwell sm_103a) ----------------
__device__ __forceinline__ u64 pack2(float a, float b) {
    u64 r; asm("mov.b64 %0, {%1, %2};" : "=l"(r) : "f"(a), "f"(b)); return r;
}
__device__ __forceinline__ u64 dup2(float a) {
    u64 r; asm("mov.b64 %0, {%1, %1};" : "=l"(r) : "f"(a)); return r;
}
__device__ __forceinline__ void unpack2(u64 v, float& a, float& b) {
    asm("mov.b64 {%0, %1}, %2;" : "=f"(a), "=f"(b) : "l"(v));
}
__device__ __forceinline__ u64 ffma2(u64 a, u64 b, u64 c) {
    u64 d; asm("fma.rn.f32x2 %0, %1, %2, %3;" : "=l"(d) : "l"(a), "l"(b), "l"(c)); return d;
}
__device__ __forceinline__ u64 fmul2(u64 a, u64 b) {
    u64 d; asm("mul.rn.f32x2 %0, %1, %2;" : "=l"(d) : "l"(a), "l"(b)); return d;
}

// ---------------- scratch (static device globals; allocation-free) ----------------
__device__ float g_h [C_CH * S_SP];        // normalized x
__device__ float g_c [C_CH * S_SP];        // normalized context
__device__ float g_q [C_CH * S_SP];        // q,  layout [o][s], o = head*64 + d
__device__ float g_kv[2 * C_CH * S_SP];    // k rows 0..511, v rows 512..1023
__device__ float g_o [C_CH * S_SP];        // attention out, layout [o][s]
__device__ float g_mu[2 * NGROUPS];
__device__ float g_rstd[2 * NGROUPS];

// ---------------- group-norm statistics: one block per (tensor, group) ----------------
__global__ __launch_bounds__(512) void gn_stats_kernel(const float* __restrict__ x,
                                                       const float* __restrict__ ctx) {
    int b = blockIdx.x;                                   // 0..15
    const float* src = (b < NGROUPS ? x : ctx) + (size_t)(b & 7) * GROUP_ELEMS;
    const float4* src4 = (const float4*)src;
    float s = 0.f, sq = 0.f;
    for (int i = threadIdx.x; i < GROUP_ELEMS / 4; i += blockDim.x) {
        float4 v = src4[i];
        s  += v.x + v.y + v.z + v.w;
        sq += v.x * v.x + v.y * v.y + v.z * v.z + v.w * v.w;
    }
    __shared__ float rs[512], rq[512];
    rs[threadIdx.x] = s; rq[threadIdx.x] = sq;
    __syncthreads();
    for (int off = blockDim.x / 2; off > 0; off >>= 1) {
        if (threadIdx.x < off) {
            rs[threadIdx.x] += rs[threadIdx.x + off];
            rq[threadIdx.x] += rq[threadIdx.x + off];
        }
        __syncthreads();
    }
    if (threadIdx.x == 0) {
        float mu  = rs[0] / (float)GROUP_ELEMS;
        float var = rq[0] / (float)GROUP_ELEMS - mu * mu;
        g_mu[b]   = mu;
        g_rstd[b] = rsqrtf(var + 1e-5f);
    }
}

// ---------------- apply norm: h = (v - mu) * rstd * w[ch] + b[ch] ----------------
__global__ __launch_bounds__(256) void gn_apply_kernel(
        const float* __restrict__ x, const float* __restrict__ ctx,
        const float* __restrict__ nw, const float* __restrict__ nb,
        const float* __restrict__ cw, const float* __restrict__ cb) {
    int t = blockIdx.y;                                   // 0 = x, 1 = context
    const float4* src = (const float4*)(t ? ctx : x);
    float4* dst = (float4*)(t ? g_c : g_h);
    const float* w = t ? cw : nw;
    const float* b = t ? cb : nb;
    const int n4 = C_CH * S_SP / 4;
    for (int i = blockIdx.x * blockDim.x + threadIdx.x; i < n4; i += gridDim.x * blockDim.x) {
        int ch = (i * 4) >> 12;                           // / 4096 (float4 never crosses a channel)
        int g  = ch >> 6;
        float rstd = g_rstd[t * NGROUPS + g];
        float sw = w[ch] * rstd;
        float sb = b[ch] - g_mu[t * NGROUPS + g] * sw;    // h = v*sw + sb
        float4 v = src[i];
        v.x = v.x * sw + sb; v.y = v.y * sw + sb;
        v.z = v.z * sw + sb; v.w = v.w * sw + sb;
        dst[i] = v;
    }
}

// ---------------- SGEMM: C[m][n] = sum_k W[m][k] A[k][n] + bias[m] (+ res) ----------------
// N fixed = S_SP. Block tile 64x64, K-tile 16, 256 threads, 4x4 contiguous microtile,
// fp32x2 packed FFMA inner loop (pairs along n).
__global__ __launch_bounds__(256) void gemm64_kernel(
        const float* __restrict__ W, const float* __restrict__ A,
        const float* __restrict__ bias, const float* __restrict__ res,
        float* __restrict__ Cp, int K) {
    __shared__ float Ws[16 * 64];       // [kk][m]
    __shared__ float As[16 * 64];       // [kk][n]
    const int tx = threadIdx.x & 15, ty = threadIdx.x >> 4;
    const int m0 = blockIdx.y * 64, n0 = blockIdx.x * 64;
    u64 acc01[4] = {0, 0, 0, 0};        // (n pair 0,1) for rows i=0..3
    u64 acc23[4] = {0, 0, 0, 0};        // (n pair 2,3)
    for (int k0 = 0; k0 < K; k0 += 16) {
        __syncthreads();
        // W tile: read float4 along k, transpose-store into [kk][m] (conflict-free: m contiguous)
        {
            int i = threadIdx.x;                          // 256 threads = 64 m * 4 kk4
            int m = i & 63, kk4 = i >> 6;                 // kk4 in 0..3
            float4 wv = *(const float4*)&W[(size_t)(m0 + m) * K + k0 + kk4 * 4];
            Ws[(kk4 * 4 + 0) * 64 + m] = wv.x;
            Ws[(kk4 * 4 + 1) * 64 + m] = wv.y;
            Ws[(kk4 * 4 + 2) * 64 + m] = wv.z;
            Ws[(kk4 * 4 + 3) * 64 + m] = wv.w;
        }
        // A tile: float4 copy
        {
            int i = threadIdx.x;                          // 256 = 16 kk * 16 n4
            int kk = i >> 4, nv = i & 15;
            ((float4*)As)[kk * 16 + nv] =
                *(const float4*)&A[(size_t)(k0 + kk) * S_SP + n0 + nv * 4];
        }
        __syncthreads();
        #pragma unroll
        for (int kk = 0; kk < 16; kk++) {
            float4 wv = *(const float4*)&Ws[kk * 64 + ty * 4];        // broadcast
            u64 a01 = *(const u64*)&As[kk * 64 + tx * 4];             // LDS.64 pair
            u64 a23 = *(const u64*)&As[kk * 64 + tx * 4 + 2];
            u64 w0 = dup2(wv.x), w1 = dup2(wv.y), w2 = dup2(wv.z), w3 = dup2(wv.w);
            acc01[0] = ffma2(w0, a01, acc01[0]); acc23[0] = ffma2(w0, a23, acc23[0]);
            acc01[1] = ffma2(w1, a01, acc01[1]); acc23[1] = ffma2(w1, a23, acc23[1]);
            acc01[2] = ffma2(w2, a01, acc01[2]); acc23[2] = ffma2(w2, a23, acc23[2]);
            acc01[3] = ffma2(w3, a01, acc01[3]); acc23[3] = ffma2(w3, a23, acc23[3]);
        }
    }
    #pragma unroll
    for (int i = 0; i < 4; i++) {
        int m = m0 + ty * 4 + i;
        float bv = bias[m];
        float c0, c1, c2, c3;
        unpack2(acc01[i], c0, c1);
        unpack2(acc23[i], c2, c3);
        float4 v = make_float4(c0 + bv, c1 + bv, c2 + bv, c3 + bv);
        size_t base = (size_t)m * S_SP + n0 + tx * 4;
        if (res) {
            float4 r = *(const float4*)&res[base];
            v.x += r.x; v.y += r.y; v.z += r.z; v.w += r.w;
        }
        *(float4*)&Cp[base] = v;
    }
}

// ---------------- flash attention: block = (64-query tile, head) ----------------
// q/k/v stored [o][s] with o = head*64 + d. Online softmax, 64-key tiles.
// Qs [d][qi] pitch 64; K [d][kj] pitch 68 (region shared with V^T [kj][d] pitch 68);
// P [qi][kj] pitch 68.  4x4 contiguous microtiles, fp32x2 packed FFMA.
#define PK 68
__global__ __launch_bounds__(256) void attn_kernel() {
    extern __shared__ float sm[];
    float* Qs  = sm;                  // 64*64
    float* KVs = sm + 64 * 64;        // 64*68 (K then V^T)
    float* Ps  = KVs + 64 * PK;       // 64*68
    const int head = blockIdx.y;
    const int q0   = blockIdx.x * 64;
    const int tx = threadIdx.x & 15, ty = threadIdx.x >> 4;

    const float* qp = g_q  + (size_t)head * HD * S_SP;
    const float* kp = g_kv + (size_t)head * HD * S_SP;
    const float* vp = g_kv + (size_t)(C_CH + head * HD) * S_SP;

    // Q tile, scale folded; float4 copy
    for (int i = threadIdx.x; i < 64 * 16; i += 256) {
        int d = i >> 4, qv = i & 15;
        float4 v = *(const float4*)&qp[(size_t)d * S_SP + q0 + qv * 4];
        v.x *= 0.125f; v.y *= 0.125f; v.z *= 0.125f; v.w *= 0.125f;
        ((float4*)Qs)[d * 16 + qv] = v;
    }

    float m[4], l[4];
    u64 o01[4] = {0, 0, 0, 0};        // (d pair 0,1) for rows i=0..3
    u64 o23[4] = {0, 0, 0, 0};        // (d pair 2,3)
    #pragma unroll
    for (int i = 0; i < 4; i++) { m[i] = -INFINITY; l[i] = 0.f; }

    for (int kt = 0; kt < S_SP / 64; kt++) {
        const int k0 = kt * 64;
        __syncthreads();                                   // prev iter done with KVs/Ps
        // K tile [d][kj] pitch 68, float4 copy
        for (int i = threadIdx.x; i < 64 * 16; i += 256) {
            int d = i >> 4, kv = i & 15;
            float4 v = *(const float4*)&kp[(size_t)d * S_SP + k0 + kv * 4];
            *(float4*)&KVs[d * PK + kv * 4] = v;
        }
        __syncthreads();

        // S = Q^T K : rows qi = ty*4+i, cols kj = tx*4+j  (packed over j)
        u64 s01[4] = {0, 0, 0, 0};
        u64 s23[4] = {0, 0, 0, 0};
        #pragma unroll 8
        for (int d = 0; d < 64; d++) {
            float4 qv = *(const float4*)&Qs[d * 64 + ty * 4];          // broadcast
            u64 k01 = *(const u64*)&KVs[d * PK + tx * 4];              // LDS.64 pair
            u64 k23 = *(const u64*)&KVs[d * PK + tx * 4 + 2];
            u64 q0d = dup2(qv.x), q1d = dup2(qv.y), q2d = dup2(qv.z), q3d = dup2(qv.w);
            s01[0] = ffma2(q0d, k01, s01[0]); s23[0] = ffma2(q0d, k23, s23[0]);
            s01[1] = ffma2(q1d, k01, s01[1]); s23[1] = ffma2(q1d, k23, s23[1]);
            s01[2] = ffma2(q2d, k01, s01[2]); s23[2] = ffma2(q2d, k23, s23[2]);
            s01[3] = ffma2(q3d, k01, s01[3]); s23[3] = ffma2(q3d, k23, s23[3]);
        }

        // online softmax (row reduction across the 16 tx lanes via shfl)
        float s[4][4];
        #pragma unroll
        for (int i = 0; i < 4; i++) {
            unpack2(s01[i], s[i][0], s[i][1]);
            unpack2(s23[i], s[i][2], s[i][3]);
            float rm = fmaxf(fmaxf(s[i][0], s[i][1]), fmaxf(s[i][2], s[i][3]));
            #pragma unroll
            for (int off = 1; off < 16; off <<= 1)
                rm = fmaxf(rm, __shfl_xor_sync(0xffffffffu, rm, off));
            float nm = fmaxf(m[i], rm);
            float cr = __expf(m[i] - nm);
            float rs = 0.f;
            #pragma unroll
            for (int j = 0; j < 4; j++) { s[i][j] = __expf(s[i][j] - nm); rs += s[i][j]; }
            #pragma unroll
            for (int off = 1; off < 16; off <<= 1)
                rs += __shfl_xor_sync(0xffffffffu, rs, off);
            l[i] = l[i] * cr + rs;
            u64 crd = dup2(cr);
            o01[i] = fmul2(o01[i], crd);
            o23[i] = fmul2(o23[i], crd);
            m[i] = nm;
        }

        __syncthreads();                                   // QK done reading K
        // P write (float4 rows), V^T load overwriting K region
        #pragma unroll
        for (int i = 0; i < 4; i++)
            *(float4*)&Ps[(ty * 4 + i) * PK + tx * 4] =
                make_float4(s[i][0], s[i][1], s[i][2], s[i][3]);
        for (int i = threadIdx.x; i < 64 * 64; i += 256) {
            int d = i >> 6, kj = i & 63;
            KVs[kj * PK + d] = vp[(size_t)d * S_SP + k0 + kj];   // transpose: V^T [kj][d]
        }
        __syncthreads();

        // O += P V : rows qi = ty*4+i, cols d = tx*4+j  (packed over d-pairs)
        #pragma unroll 8
        for (int kj = 0; kj < 64; kj++) {
            u64 v01 = *(const u64*)&KVs[kj * PK + tx * 4];             // LDS.64 pair
            u64 v23 = *(const u64*)&KVs[kj * PK + tx * 4 + 2];
            float p0 = Ps[(ty * 4 + 0) * PK + kj];                     // broadcast
            float p1 = Ps[(ty * 4 + 1) * PK + kj];
            float p2 = Ps[(ty * 4 + 2) * PK + kj];
            float p3 = Ps[(ty * 4 + 3) * PK + kj];
            u64 p0d = dup2(p0), p1d = dup2(p1), p2d = dup2(p2), p3d = dup2(p3);
            o01[0] = ffma2(p0d, v01, o01[0]); o23[0] = ffma2(p0d, v23, o23[0]);
            o01[1] = ffma2(p1d, v01, o01[1]); o23[1] = ffma2(p1d, v23, o23[1]);
            o01[2] = ffma2(p2d, v01, o01[2]); o23[2] = ffma2(p2d, v23, o23[2]);
            o01[3] = ffma2(p3d, v01, o01[3]); o23[3] = ffma2(p3d, v23, o23[3]);
        }
    }

    // stage O into smem (reuse Ps region, pitch 65) then coalesced copyout [d][qi]
    float* Os = Ps;                    // 64*65 = 4160 <= 64*68 = 4352
    __syncthreads();                   // everyone done with final PV (Ps reads)
    #pragma unroll
    for (int i = 0; i < 4; i++) {
        float inv = 1.f / l[i];
        float o0, o1, o2, o3;
        unpack2(o01[i], o0, o1);
        unpack2(o23[i], o2, o3);
        Os[(tx * 4 + 0) * 65 + ty * 4 + i] = o0 * inv;    // [d][qi]
        Os[(tx * 4 + 1) * 65 + ty * 4 + i] = o1 * inv;
        Os[(tx * 4 + 2) * 65 + ty * 4 + i] = o2 * inv;
        Os[(tx * 4 + 3) * 65 + ty * 4 + i] = o3 * inv;
    }
    __syncthreads();
    for (int i = threadIdx.x; i < 64 * 64; i += 256) {
        int d = i >> 6, qi = i & 63;
        g_o[(size_t)(head * HD + d) * S_SP + q0 + qi] = Os[d * 65 + qi];
    }
}

// ---------------- launch ----------------
extern "C" void kernel_launch(void* const* d_in, const int* in_sizes, int n_in,
                              void* d_out, int out_size) {
    const float* x       = (const float*)d_in[0];
    const float* context = (const float*)d_in[1];
    const float* norm_w  = (const float*)d_in[2];
    const float* norm_b  = (const float*)d_in[3];
    const float* normc_w = (const float*)d_in[4];
    const float* normc_b = (const float*)d_in[5];
    const float* q_w     = (const float*)d_in[6];
    const float* q_b     = (const float*)d_in[7];
    const float* kv_w    = (const float*)d_in[8];
    const float* kv_b    = (const float*)d_in[9];
    const float* proj_w  = (const float*)d_in[10];
    const float* proj_b  = (const float*)d_in[11];
    float* out = (float*)d_out;

    float *p_h, *p_c, *p_q, *p_kv, *p_o;
    cudaGetSymbolAddress((void**)&p_h,  g_h);
    cudaGetSymbolAddress((void**)&p_c,  g_c);
    cudaGetSymbolAddress((void**)&p_q,  g_q);
    cudaGetSymbolAddress((void**)&p_kv, g_kv);
    cudaGetSymbolAddress((void**)&p_o,  g_o);

    const int attn_smem = (64 * 64 + 2 * 64 * PK) * (int)sizeof(float);   // 51200 B
    cudaFuncSetAttribute(attn_kernel, cudaFuncAttributeMaxDynamicSharedMemorySize, attn_smem);

    // 1) group-norm stats for x and context
    gn_stats_kernel<<<2 * NGROUPS, 512>>>(x, context);
    // 2) normalize -> g_h, g_c
    gn_apply_kernel<<<dim3(256, 2), 256>>>(x, context, norm_w, norm_b, normc_w, normc_b);
    // 3) q = q_w @ h + q_b           -> g_q  [512][4096]
    gemm64_kernel<<<dim3(S_SP / 64, C_CH / 64), 256>>>(q_w, p_h, q_b, nullptr, p_q, C_CH);
    // 4) kv = kv_w @ c + kv_b        -> g_kv [1024][4096]
    gemm64_kernel<<<dim3(S_SP / 64, 2 * C_CH / 64), 256>>>(kv_w, p_c, kv_b, nullptr, p_kv, C_CH);
    // 5) attention -> g_o [512][4096]
    attn_kernel<<<dim3(S_SP / 64, NHEADS), 256, attn_smem>>>();
    // 6) out = proj_w @ attn + proj_b + x
    gemm64_kernel<<<dim3(S_SP / 64, C_CH / 64), 256>>>(proj_w, p_o, proj_b, x, out, C_CH);
}

// round 12
// speedup vs baseline: 2.1141x; 2.1141x over previous
#include <cuda_runtime.h>
#include <math.h>

#define C_CH   512
#define S_SP   4096
#define NHEADS 8
#define HD     64
#define NGROUPS 8
#define GROUP_ELEMS ((C_CH / NGROUPS) * S_SP)   // 64 ch * 4096 = 262144

typedef unsigned long long u64;
typedef unsigned int u32;

// ---------------- packed fp32x2 helpers (Blackwell sm_103a) ----------------
__device__ __forceinline__ u64 dup2(float a) {
    u64 r; asm("mov.b64 %0, {%1, %1};" : "=l"(r) : "f"(a)); return r;
}
__device__ __forceinline__ void unpack2(u64 v, float& a, float& b) {
    asm("mov.b64 {%0, %1}, %2;" : "=f"(a), "=f"(b) : "l"(v));
}
__device__ __forceinline__ u64 ffma2(u64 a, u64 b, u64 c) {
    u64 d; asm("fma.rn.f32x2 %0, %1, %2, %3;" : "=l"(d) : "l"(a), "l"(b), "l"(c)); return d;
}

// ---------------- tf32 mma.sync m16n8k8 ----------------
__device__ __forceinline__ void mma_tf32(float& c0, float& c1, float& c2, float& c3,
                                         u32 a0, u32 a1, u32 a2, u32 a3,
                                         u32 b0, u32 b1) {
    asm volatile(
        "mma.sync.aligned.m16n8k8.row.col.f32.tf32.tf32.f32 "
        "{%0,%1,%2,%3}, {%4,%5,%6,%7}, {%8,%9}, {%0,%1,%2,%3};"
        : "+f"(c0), "+f"(c1), "+f"(c2), "+f"(c3)
        : "r"(a0), "r"(a1), "r"(a2), "r"(a3), "r"(b0), "r"(b1));
}

// ---------------- scratch (static device globals; allocation-free) ----------------
__device__ float g_h [C_CH * S_SP];        // normalized x
__device__ float g_c [C_CH * S_SP];        // normalized context
__device__ float g_q [C_CH * S_SP];        // q,  layout [o][s], o = head*64 + d
__device__ float g_kv[2 * C_CH * S_SP];    // k rows 0..511, v rows 512..1023
__device__ float g_o [C_CH * S_SP];        // attention out, layout [o][s]
__device__ float g_mu[2 * NGROUPS];
__device__ float g_rstd[2 * NGROUPS];

// ---------------- group-norm statistics: one block per (tensor, group) ----------------
__global__ __launch_bounds__(512) void gn_stats_kernel(const float* __restrict__ x,
                                                       const float* __restrict__ ctx) {
    int b = blockIdx.x;                                   // 0..15
    const float* src = (b < NGROUPS ? x : ctx) + (size_t)(b & 7) * GROUP_ELEMS;
    const float4* src4 = (const float4*)src;
    float s = 0.f, sq = 0.f;
    for (int i = threadIdx.x; i < GROUP_ELEMS / 4; i += blockDim.x) {
        float4 v = src4[i];
        s  += v.x + v.y + v.z + v.w;
        sq += v.x * v.x + v.y * v.y + v.z * v.z + v.w * v.w;
    }
    __shared__ float rs[512], rq[512];
    rs[threadIdx.x] = s; rq[threadIdx.x] = sq;
    __syncthreads();
    for (int off = blockDim.x / 2; off > 0; off >>= 1) {
        if (threadIdx.x < off) {
            rs[threadIdx.x] += rs[threadIdx.x + off];
            rq[threadIdx.x] += rq[threadIdx.x + off];
        }
        __syncthreads();
    }
    if (threadIdx.x == 0) {
        float mu  = rs[0] / (float)GROUP_ELEMS;
        float var = rq[0] / (float)GROUP_ELEMS - mu * mu;
        g_mu[b]   = mu;
        g_rstd[b] = rsqrtf(var + 1e-5f);
    }
}

// ---------------- apply norm: h = (v - mu) * rstd * w[ch] + b[ch] ----------------
__global__ __launch_bounds__(256) void gn_apply_kernel(
        const float* __restrict__ x, const float* __restrict__ ctx,
        const float* __restrict__ nw, const float* __restrict__ nb,
        const float* __restrict__ cw, const float* __restrict__ cb) {
    int t = blockIdx.y;                                   // 0 = x, 1 = context
    const float4* src = (const float4*)(t ? ctx : x);
    float4* dst = (float4*)(t ? g_c : g_h);
    const float* w = t ? cw : nw;
    const float* b = t ? cb : nb;
    const int n4 = C_CH * S_SP / 4;
    for (int i = blockIdx.x * blockDim.x + threadIdx.x; i < n4; i += gridDim.x * blockDim.x) {
        int ch = (i * 4) >> 12;                           // / 4096
        int g  = ch >> 6;
        float rstd = g_rstd[t * NGROUPS + g];
        float sw = w[ch] * rstd;
        float sb = b[ch] - g_mu[t * NGROUPS + g] * sw;    // h = v*sw + sb
        float4 v = src[i];
        v.x = v.x * sw + sb; v.y = v.y * sw + sb;
        v.z = v.z * sw + sb; v.w = v.w * sw + sb;
        dst[i] = v;
    }
}

// ---------------- SGEMM: unchanged (verified, f32x2 FFMA2) ----------------
__global__ __launch_bounds__(256) void gemm64_kernel(
        const float* __restrict__ W, const float* __restrict__ A,
        const float* __restrict__ bias, const float* __restrict__ res,
        float* __restrict__ Cp, int K) {
    __shared__ float Ws[16 * 64];       // [kk][m]
    __shared__ float As[16 * 64];       // [kk][n]
    const int tx = threadIdx.x & 15, ty = threadIdx.x >> 4;
    const int m0 = blockIdx.y * 64, n0 = blockIdx.x * 64;
    u64 acc01[4] = {0, 0, 0, 0};
    u64 acc23[4] = {0, 0, 0, 0};
    for (int k0 = 0; k0 < K; k0 += 16) {
        __syncthreads();
        {
            int i = threadIdx.x;
            int m = i & 63, kk4 = i >> 6;
            float4 wv = *(const float4*)&W[(size_t)(m0 + m) * K + k0 + kk4 * 4];
            Ws[(kk4 * 4 + 0) * 64 + m] = wv.x;
            Ws[(kk4 * 4 + 1) * 64 + m] = wv.y;
            Ws[(kk4 * 4 + 2) * 64 + m] = wv.z;
            Ws[(kk4 * 4 + 3) * 64 + m] = wv.w;
        }
        {
            int i = threadIdx.x;
            int kk = i >> 4, nv = i & 15;
            ((float4*)As)[kk * 16 + nv] =
                *(const float4*)&A[(size_t)(k0 + kk) * S_SP + n0 + nv * 4];
        }
        __syncthreads();
        #pragma unroll
        for (int kk = 0; kk < 16; kk++) {
            float4 wv = *(const float4*)&Ws[kk * 64 + ty * 4];
            u64 a01 = *(const u64*)&As[kk * 64 + tx * 4];
            u64 a23 = *(const u64*)&As[kk * 64 + tx * 4 + 2];
            u64 w0 = dup2(wv.x), w1 = dup2(wv.y), w2 = dup2(wv.z), w3 = dup2(wv.w);
            acc01[0] = ffma2(w0, a01, acc01[0]); acc23[0] = ffma2(w0, a23, acc23[0]);
            acc01[1] = ffma2(w1, a01, acc01[1]); acc23[1] = ffma2(w1, a23, acc23[1]);
            acc01[2] = ffma2(w2, a01, acc01[2]); acc23[2] = ffma2(w2, a23, acc23[2]);
            acc01[3] = ffma2(w3, a01, acc01[3]); acc23[3] = ffma2(w3, a23, acc23[3]);
        }
    }
    #pragma unroll
    for (int i = 0; i < 4; i++) {
        int m = m0 + ty * 4 + i;
        float bv = bias[m];
        float c0, c1, c2, c3;
        unpack2(acc01[i], c0, c1);
        unpack2(acc23[i], c2, c3);
        float4 v = make_float4(c0 + bv, c1 + bv, c2 + bv, c3 + bv);
        size_t base = (size_t)m * S_SP + n0 + tx * 4;
        if (res) {
            float4 r = *(const float4*)&res[base];
            v.x += r.x; v.y += r.y; v.z += r.z; v.w += r.w;
        }
        *(float4*)&Cp[base] = v;
    }
}

// ---------------- tf32 mma flash attention ----------------
// Block = (q-tile 128, head). 8 warps; warp w owns q-rows [16w, 16w+16).
// smem: region0 = Q staging [d][qi] 64 x PQ (reused as P [qi][kj] 128 x PP after
// Q fragments are register-resident); Ks/Vs = K,V tiles [d][kj] 64 x PKV.
// All fragment-load patterns conflict-free (pitch ≡ 4 mod 32).
#define PQ   132
#define PP   68
#define PKV  68
#define R0F  8704                 // floats in region0 (= 128*68)
#define ATT_SMEM ((R0F + 2 * 64 * PKV) * 4)   // 69632 B

__global__ __launch_bounds__(256) void attn_mma_kernel() {
    extern __shared__ float sm[];
    float* Qs = sm;               // 64 x PQ (8448 <= 8704)
    float* Ps = sm;               // 128 x PP (= 8704)
    float* Ks = sm + R0F;         // 64 x PKV
    float* Vs = Ks + 64 * PKV;    // 64 x PKV

    const int head = blockIdx.y;
    const int q0   = blockIdx.x * 128;
    const int tid  = threadIdx.x;
    const int warp = tid >> 5, lane = tid & 31;
    const int g = lane >> 2, t = lane & 3;        // groupID, threadID_in_group
    const int r0 = warp * 16 + g;                 // local q-row of c0/c1
    const int r1 = r0 + 8;                        // local q-row of c2/c3

    const float* qp = g_q  + (size_t)head * HD * S_SP;
    const float* kp = g_kv + (size_t)head * HD * S_SP;
    const float* vp = g_kv + (size_t)(C_CH + head * HD) * S_SP;

    // ---- stage Q [d][qi] (scale folded), coalesced float4 ----
    for (int i = tid; i < 64 * 32; i += 256) {
        int d = i >> 5, qv = i & 31;
        float4 v = *(const float4*)&qp[(size_t)d * S_SP + q0 + qv * 4];
        v.x *= 0.125f; v.y *= 0.125f; v.z *= 0.125f; v.w *= 0.125f;
        *(float4*)&Qs[d * PQ + qv * 4] = v;
    }
    __syncthreads();

    // ---- build Q A-fragments in registers (reused for all K-tiles) ----
    // A[m][k] = Q[q0 + 16w + m][d0 + k];  a0=(g,t) a1=(g+8,t) a2=(g,t+4) a3=(g+8,t+4)
    u32 qA[8][4];
    #pragma unroll
    for (int ks = 0; ks < 8; ks++) {
        int d0 = ks * 8;
        qA[ks][0] = __float_as_uint(Qs[(d0 + t)     * PQ + r0]);
        qA[ks][1] = __float_as_uint(Qs[(d0 + t)     * PQ + r1]);
        qA[ks][2] = __float_as_uint(Qs[(d0 + t + 4) * PQ + r0]);
        qA[ks][3] = __float_as_uint(Qs[(d0 + t + 4) * PQ + r1]);
    }
    __syncthreads();              // done with Qs; region becomes Ps

    float o[8][4];                // O fragments: 16 x 64 per warp (d-tiles)
    #pragma unroll
    for (int nt = 0; nt < 8; nt++)
        #pragma unroll
        for (int c = 0; c < 4; c++) o[nt][c] = 0.f;
    float m0 = -1e30f, m1 = -1e30f, l0 = 0.f, l1 = 0.f;

    for (int kt = 0; kt < S_SP / 64; kt++) {
        const int k0g = kt * 64;
        __syncthreads();          // prev iter done reading Ks/Vs/Ps
        // ---- load K,V tiles [d][kj], coalesced float4, no transpose ----
        for (int i = tid; i < 64 * 16; i += 256) {
            int d = i >> 4, c = i & 15;
            *(float4*)&Ks[d * PKV + c * 4] =
                *(const float4*)&kp[(size_t)d * S_SP + k0g + c * 4];
            *(float4*)&Vs[d * PKV + c * 4] =
                *(const float4*)&vp[(size_t)d * S_SP + k0g + c * 4];
        }
        __syncthreads();

        // ---- S = Q K^T : B[k][n] = K[kj0+n][d0+k] = Ks[(d0+k)*PKV + kj0+n] ----
        float s[8][4];
        #pragma unroll
        for (int nt = 0; nt < 8; nt++)
            #pragma unroll
            for (int c = 0; c < 4; c++) s[nt][c] = 0.f;
        #pragma unroll
        for (int ks = 0; ks < 8; ks++) {
            int d0 = ks * 8;
            #pragma unroll
            for (int nt = 0; nt < 8; nt++) {
                int n0 = nt * 8;
                u32 b0 = __float_as_uint(Ks[(d0 + t)     * PKV + n0 + g]);
                u32 b1 = __float_as_uint(Ks[(d0 + t + 4) * PKV + n0 + g]);
                mma_tf32(s[nt][0], s[nt][1], s[nt][2], s[nt][3],
                         qA[ks][0], qA[ks][1], qA[ks][2], qA[ks][3], b0, b1);
            }
        }

        // ---- online softmax (rows r0, r1; quad shfl over the 4 lanes of a row) ----
        float rm0 = -1e30f, rm1 = -1e30f;
        #pragma unroll
        for (int nt = 0; nt < 8; nt++) {
            rm0 = fmaxf(rm0, fmaxf(s[nt][0], s[nt][1]));
            rm1 = fmaxf(rm1, fmaxf(s[nt][2], s[nt][3]));
        }
        rm0 = fmaxf(rm0, __shfl_xor_sync(0xffffffffu, rm0, 1));
        rm0 = fmaxf(rm0, __shfl_xor_sync(0xffffffffu, rm0, 2));
        rm1 = fmaxf(rm1, __shfl_xor_sync(0xffffffffu, rm1, 1));
        rm1 = fmaxf(rm1, __shfl_xor_sync(0xffffffffu, rm1, 2));
        float nm0 = fmaxf(m0, rm0), nm1 = fmaxf(m1, rm1);
        float cr0 = __expf(m0 - nm0), cr1 = __expf(m1 - nm1);
        float rs0 = 0.f, rs1 = 0.f;
        #pragma unroll
        for (int nt = 0; nt < 8; nt++) {
            s[nt][0] = __expf(s[nt][0] - nm0);
            s[nt][1] = __expf(s[nt][1] - nm0);
            s[nt][2] = __expf(s[nt][2] - nm1);
            s[nt][3] = __expf(s[nt][3] - nm1);
            rs0 += s[nt][0] + s[nt][1];
            rs1 += s[nt][2] + s[nt][3];
        }
        rs0 += __shfl_xor_sync(0xffffffffu, rs0, 1);
        rs0 += __shfl_xor_sync(0xffffffffu, rs0, 2);
        rs1 += __shfl_xor_sync(0xffffffffu, rs1, 1);
        rs1 += __shfl_xor_sync(0xffffffffu, rs1, 2);
        l0 = l0 * cr0 + rs0;  l1 = l1 * cr1 + rs1;
        m0 = nm0;  m1 = nm1;
        #pragma unroll
        for (int nt = 0; nt < 8; nt++) {
            o[nt][0] *= cr0; o[nt][1] *= cr0;
            o[nt][2] *= cr1; o[nt][3] *= cr1;
        }

        // ---- write P strip (warp-private rows), reload as A-fragments ----
        #pragma unroll
        for (int nt = 0; nt < 8; nt++) {
            *(float2*)&Ps[r0 * PP + nt * 8 + 2 * t] = make_float2(s[nt][0], s[nt][1]);
            *(float2*)&Ps[r1 * PP + nt * 8 + 2 * t] = make_float2(s[nt][2], s[nt][3]);
        }
        __syncwarp();

        // ---- O += P V : B[k][n] = V[kj0+k][d0+n] = Vs[(d0+n)*PKV + kj0+k] ----
        #pragma unroll
        for (int ks = 0; ks < 8; ks++) {
            int kj0 = ks * 8;
            u32 a0 = __float_as_uint(Ps[r0 * PP + kj0 + t]);
            u32 a1 = __float_as_uint(Ps[r1 * PP + kj0 + t]);
            u32 a2 = __float_as_uint(Ps[r0 * PP + kj0 + t + 4]);
            u32 a3 = __float_as_uint(Ps[r1 * PP + kj0 + t + 4]);
            #pragma unroll
            for (int nt = 0; nt < 8; nt++) {
                int d0 = nt * 8;
                u32 b0 = __float_as_uint(Vs[(d0 + g) * PKV + kj0 + t]);
                u32 b1 = __float_as_uint(Vs[(d0 + g) * PKV + kj0 + t + 4]);
                mma_tf32(o[nt][0], o[nt][1], o[nt][2], o[nt][3],
                         a0, a1, a2, a3, b0, b1);
            }
        }
    }

    // ---- normalize, stage O [d][qi] in Ks/Vs region, coalesced copyout ----
    float inv0 = 1.f / l0, inv1 = 1.f / l1;
    float* Os = Ks;               // 64 x 132 = 8448 floats <= 8704 (Ks+Vs region)
    __syncthreads();              // all warps done with Vs reads
    #pragma unroll
    for (int nt = 0; nt < 8; nt++) {
        int d0 = nt * 8 + 2 * t;
        Os[(d0 + 0) * PQ + r0] = o[nt][0] * inv0;
        Os[(d0 + 1) * PQ + r0] = o[nt][1] * inv0;
        Os[(d0 + 0) * PQ + r1] = o[nt][2] * inv1;
        Os[(d0 + 1) * PQ + r1] = o[nt][3] * inv1;
    }
    __syncthreads();
    for (int i = tid; i < 64 * 128; i += 256) {
        int d = i >> 7, qi = i & 127;
        g_o[(size_t)(head * HD + d) * S_SP + q0 + qi] = Os[d * PQ + qi];
    }
}

// ---------------- launch ----------------
extern "C" void kernel_launch(void* const* d_in, const int* in_sizes, int n_in,
                              void* d_out, int out_size) {
    const float* x       = (const float*)d_in[0];
    const float* context = (const float*)d_in[1];
    const float* norm_w  = (const float*)d_in[2];
    const float* norm_b  = (const float*)d_in[3];
    const float* normc_w = (const float*)d_in[4];
    const float* normc_b = (const float*)d_in[5];
    const float* q_w     = (const float*)d_in[6];
    const float* q_b     = (const float*)d_in[7];
    const float* kv_w    = (const float*)d_in[8];
    const float* kv_b    = (const float*)d_in[9];
    const float* proj_w  = (const float*)d_in[10];
    const float* proj_b  = (const float*)d_in[11];
    float* out = (float*)d_out;

    float *p_h, *p_c, *p_q, *p_kv, *p_o;
    cudaGetSymbolAddress((void**)&p_h,  g_h);
    cudaGetSymbolAddress((void**)&p_c,  g_c);
    cudaGetSymbolAddress((void**)&p_q,  g_q);
    cudaGetSymbolAddress((void**)&p_kv, g_kv);
    cudaGetSymbolAddress((void**)&p_o,  g_o);

    cudaFuncSetAttribute(attn_mma_kernel,
                         cudaFuncAttributeMaxDynamicSharedMemorySize, ATT_SMEM);

    // 1) group-norm stats
    gn_stats_kernel<<<2 * NGROUPS, 512>>>(x, context);
    // 2) normalize -> g_h, g_c
    gn_apply_kernel<<<dim3(256, 2), 256>>>(x, context, norm_w, norm_b, normc_w, normc_b);
    // 3) q = q_w @ h + q_b           -> g_q  [512][4096]
    gemm64_kernel<<<dim3(S_SP / 64, C_CH / 64), 256>>>(q_w, p_h, q_b, nullptr, p_q, C_CH);
    // 4) kv = kv_w @ c + kv_b        -> g_kv [1024][4096]
    gemm64_kernel<<<dim3(S_SP / 64, 2 * C_CH / 64), 256>>>(kv_w, p_c, kv_b, nullptr, p_kv, C_CH);
    // 5) attention (tf32 tensor cores) -> g_o [512][4096]
    attn_mma_kernel<<<dim3(S_SP / 128, NHEADS), 256, ATT_SMEM>>>();
    // 6) out = proj_w @ attn + proj_b + x
    gemm64_kernel<<<dim3(S_SP / 64, C_CH / 64), 256>>>(proj_w, p_o, proj_b, x, out, C_CH);
}